// round 4
// baseline (speedup 1.0000x reference)
#include <cuda_runtime.h>
#include <cstdint>

// out[r,t] = sum_{k=0}^{K-1} kernel[K-1-k] * u[r, t+k]
// Two batch rows packed into f32x2 lanes, 16 consecutive outputs per thread
// via a 16-deep register ring window, packed fma.rn.f32x2, swizzle-padded
// SMEM with fully hoisted address arithmetic (immediate-offset LDS).

#define BLOCK 256
#define OPT   16
#define TT    (BLOCK * OPT)      // 4096 outputs per block (per row pair)
#define KMAX  128
#define LOADN (TT + KMAX)        // 4224 input positions staged per block

typedef unsigned long long ull;

__device__ __forceinline__ ull fma2(ull a, ull b, ull c) {
    ull d;
    asm("fma.rn.f32x2 %0, %1, %2, %3;" : "=l"(d) : "l"(a), "l"(b), "l"(c));
    return d;
}

// pad 1 float2 per 16 -> stride-16-float2 accesses become a perfect bank permutation
__device__ __forceinline__ int slot(int i) { return i + (i >> 4); }

__global__ __launch_bounds__(BLOCK)
void conv2row(const float* __restrict__ u, const float* __restrict__ kern,
              float* __restrict__ out, int T_out, int T_in, int K)
{
    __shared__ float2 s_u[LOADN + (LOADN >> 4) + 2];   // padded layout
    __shared__ __align__(16) float2 s_w[KMAX];

    const int tid  = threadIdx.x;
    const int base = blockIdx.x * TT;
    const long r0  = (long)blockIdx.y * 2;
    const float* __restrict__ u0 = u + r0 * (long)T_in;
    const float* __restrict__ u1 = u0 + T_in;

    // reversed kernel, broadcast-packed (w,w); zero padded to KMAX
    for (int i = tid; i < KMAX; i += BLOCK) {
        float w = (i < K) ? kern[K - 1 - i] : 0.0f;
        s_w[i] = make_float2(w, w);
    }

    // stage input tile: s_u[i] = (u0[base+i], u1[base+i]); zero beyond row end
    for (int i = tid * 4; i < LOADN; i += BLOCK * 4) {
        int g = base + i;
        float4 a, b;
        if (g + 3 < T_in) {
            a = *(const float4*)(u0 + g);
            b = *(const float4*)(u1 + g);
        } else {
            float av[4], bv[4];
            #pragma unroll
            for (int e = 0; e < 4; ++e) {
                int gg = g + e;
                av[e] = (gg < T_in) ? u0[gg] : 0.0f;
                bv[e] = (gg < T_in) ? u1[gg] : 0.0f;
            }
            a = make_float4(av[0], av[1], av[2], av[3]);
            b = make_float4(bv[0], bv[1], bv[2], bv[3]);
        }
        s_u[slot(i + 0)] = make_float2(a.x, b.x);
        s_u[slot(i + 1)] = make_float2(a.y, b.y);
        s_u[slot(i + 2)] = make_float2(a.z, b.z);
        s_u[slot(i + 3)] = make_float2(a.w, b.w);
    }
    __syncthreads();

    const int toff = tid * OPT;          // multiple of 16
    const int t0   = base + toff;
    if (t0 >= T_out) return;             // no barriers after this point

    // toff % 16 == 0 => slot(toff + x) == slot(toff) + slot(x) exactly.
    // All inner-loop shared addresses become [pu + kq + imm].
    const float2* __restrict__ pu = s_u + slot(toff);

    ull acc[OPT];
    #pragma unroll
    for (int i = 0; i < OPT; ++i) acc[i] = 0ull;

    // ring: before weight step m, win[(m+i)&15] = packed u at position toff+m+i
    ull win[OPT];
    #pragma unroll
    for (int j = 0; j < OPT; ++j) win[j] = *(const ull*)(pu + j);  // slot(j)==j for j<16

    const int nfull = K >> 4;
    const int rem   = K & 15;
    int kq = 0;      // slot-advance of k: k + (k>>4), += 17 per round of 16
    int kw = 0;      // weight base index

    for (int it = 0; it < nfull; ++it, kq += 17, kw += 16) {
        #pragma unroll
        for (int kk2 = 0; kk2 < 8; ++kk2) {
            // two packed (w,w) weights per 16B shared load
            ulonglong2 wp = *(const ulonglong2*)&s_w[kw + 2 * kk2];
            {
                const int kk = 2 * kk2;
                #pragma unroll
                for (int i = 0; i < OPT; ++i)
                    acc[i] = fma2(wp.x, win[(kk + i) & 15], acc[i]);
                // refill position toff+kw+kk+16 -> offset slot(kk+16) = kk+17
                win[kk] = *(const ull*)(pu + kq + kk + 17);
            }
            {
                const int kk = 2 * kk2 + 1;
                #pragma unroll
                for (int i = 0; i < OPT; ++i)
                    acc[i] = fma2(wp.y, win[(kk + i) & 15], acc[i]);
                win[kk] = *(const ull*)(pu + kq + kk + 17);
            }
        }
    }
    // remainder (rem < 16), predicated; refills stay within staged range
    #pragma unroll
    for (int kk = 0; kk < 15; ++kk) {
        if (kk < rem) {
            ull wv = *(const ull*)&s_w[kw + kk];
            #pragma unroll
            for (int i = 0; i < OPT; ++i)
                acc[i] = fma2(wv, win[(kk + i) & 15], acc[i]);
            win[kk] = *(const ull*)(pu + kq + kk + 17);
        }
    }

    // store: row r0 gets .x lane, row r0+1 gets .y lane
    float2 res[OPT];
    #pragma unroll
    for (int i = 0; i < OPT; ++i) res[i] = *(float2*)&acc[i];

    const long o0 = r0 * (long)T_out;
    if (t0 + OPT <= T_out) {
        float4* p0 = (float4*)(out + o0 + t0);
        float4* p1 = (float4*)(out + o0 + T_out + t0);
        #pragma unroll
        for (int q = 0; q < 4; ++q) {
            p0[q] = make_float4(res[4*q].x, res[4*q+1].x, res[4*q+2].x, res[4*q+3].x);
            p1[q] = make_float4(res[4*q].y, res[4*q+1].y, res[4*q+2].y, res[4*q+3].y);
        }
    } else {
        #pragma unroll
        for (int i = 0; i < OPT; ++i) {
            int t = t0 + i;
            if (t < T_out) {
                out[o0 + t]         = res[i].x;
                out[o0 + T_out + t] = res[i].y;
            }
        }
    }
}

// Robust fallback for any shape the fast path doesn't cover.
__global__ void conv_naive(const float* __restrict__ u, const float* __restrict__ kern,
                           float* __restrict__ out, int T_out, int T_in, int K, long total)
{
    long idx = (long)blockIdx.x * blockDim.x + threadIdx.x;
    if (idx >= total) return;
    int  t = (int)(idx % T_out);
    long r = idx / T_out;
    const float* up = u + r * (long)T_in + t;
    float acc = 0.0f;
    for (int k = 0; k < K; ++k)
        acc = fmaf(kern[K - 1 - k], up[k], acc);
    out[idx] = acc;
}

extern "C" void kernel_launch(void* const* d_in, const int* in_sizes, int n_in,
                              void* d_out, int out_size)
{
    const float* u    = (const float*)d_in[0];
    const float* kern = (const float*)d_in[1];
    float*       out  = (float*)d_out;

    const long n_u   = in_sizes[0];
    const int  K     = in_sizes[1];
    const long n_out = out_size;

    // u is (R, T_out + K - 1), out is (R, T_out)  =>  R = (n_u - n_out)/(K-1)
    long R = 1;
    if (K > 1 && (n_u - n_out) % (K - 1) == 0) {
        long r = (n_u - n_out) / (K - 1);
        if (r > 0 && n_out % r == 0 && n_u % r == 0) R = r;
    } else if (K == 1 && n_u == n_out) {
        R = 1;
    }
    const int T_out = (int)(n_out / R);
    const int T_in  = (int)(n_u / R);

    const bool fast = (K >= 1) && (K <= KMAX) && (R % 2 == 0) &&
                      (T_in % 4 == 0) && (T_out % 4 == 0) &&
                      (R * (long)T_out == n_out) && (R * (long)T_in == n_u) &&
                      (T_in >= T_out + K - 1);

    if (fast) {
        dim3 grid((T_out + TT - 1) / TT, (unsigned)(R / 2));
        conv2row<<<grid, BLOCK>>>(u, kern, out, T_out, T_in, K);
    } else {
        long total = n_out;
        int  thr = 256;
        long blocks = (total + thr - 1) / thr;
        conv_naive<<<(unsigned)blocks, thr>>>(u, kern, out, T_out, T_in, K, total);
    }
}

// round 13
// speedup vs baseline: 1.1290x; 1.1290x over previous
#include <cuda_runtime.h>
#include <cstdint>

// out[r,t] = sum_{k=0}^{K-1} kernel[K-1-k] * u[r, t+k]
// Two batch rows packed into f32x2 lanes, 8 outputs/thread via register ring,
// packed fma.rn.f32x2, pad-per-8 SMEM swizzle with fully hoisted address
// arithmetic (immediate-offset LDS), 3 CTAs/SM pinned.

#define BLOCK 256
#define OPT   8
#define TT    (BLOCK * OPT)      // 2048 outputs per block (per row pair)
#define KMAX  128
#define LOADN (TT + KMAX)        // 2176 input positions staged per block

typedef unsigned long long ull;

__device__ __forceinline__ ull fma2(ull a, ull b, ull c) {
    ull d;
    asm("fma.rn.f32x2 %0, %1, %2, %3;" : "=l"(d) : "l"(a), "l"(b), "l"(c));
    return d;
}

// pad 1 float2 per 8 -> stride-8-float2 accesses land 9 apart: 16-lane phases
// hit 16 distinct even bank-pairs -> conflict-free LDS.64
__device__ __forceinline__ int slot8(int i) { return i + (i >> 3); }

__global__ __launch_bounds__(BLOCK, 3)
void conv2row(const float* __restrict__ u, const float* __restrict__ kern,
              float* __restrict__ out, int T_out, int T_in, int K)
{
    __shared__ float2 s_u[LOADN + (LOADN >> 3) + 2];   // padded layout
    __shared__ __align__(16) float2 s_w[KMAX];

    const int tid  = threadIdx.x;
    const int base = blockIdx.x * TT;
    const long r0  = (long)blockIdx.y * 2;
    const float* __restrict__ u0 = u + r0 * (long)T_in;
    const float* __restrict__ u1 = u0 + T_in;

    // reversed kernel, broadcast-packed (w,w); zero padded to KMAX
    for (int i = tid; i < KMAX; i += BLOCK) {
        float w = (i < K) ? kern[K - 1 - i] : 0.0f;
        s_w[i] = make_float2(w, w);
    }

    // stage input tile: s_u[slot8(i)] = (u0[base+i], u1[base+i])
    for (int i = tid * 4; i < LOADN; i += BLOCK * 4) {
        int g = base + i;
        float4 a, b;
        if (g + 3 < T_in) {
            a = *(const float4*)(u0 + g);
            b = *(const float4*)(u1 + g);
        } else {
            float av[4], bv[4];
            #pragma unroll
            for (int e = 0; e < 4; ++e) {
                int gg = g + e;
                av[e] = (gg < T_in) ? u0[gg] : 0.0f;
                bv[e] = (gg < T_in) ? u1[gg] : 0.0f;
            }
            a = make_float4(av[0], av[1], av[2], av[3]);
            b = make_float4(bv[0], bv[1], bv[2], bv[3]);
        }
        s_u[slot8(i + 0)] = make_float2(a.x, b.x);
        s_u[slot8(i + 1)] = make_float2(a.y, b.y);
        s_u[slot8(i + 2)] = make_float2(a.z, b.z);
        s_u[slot8(i + 3)] = make_float2(a.w, b.w);
    }
    __syncthreads();

    const int toff = tid * OPT;          // multiple of 8
    const int t0   = base + toff;
    if (t0 >= T_out) return;             // no barriers after this point

    // toff % 8 == 0 => slot8(toff + x) == slot8(toff) + slot8(x) exactly.
    // All inner-loop shared addresses become [pu + kq + imm].
    const float2* __restrict__ pu = s_u + slot8(toff);

    ull acc[OPT];
    #pragma unroll
    for (int i = 0; i < OPT; ++i) acc[i] = 0ull;

    // ring: before weight step m, win[(m+i)&7] = packed u at position toff+m+i
    ull win[OPT];
    #pragma unroll
    for (int j = 0; j < OPT; ++j) win[j] = *(const ull*)(pu + j);  // slot8(j)==j for j<8

    const int nfull = K >> 3;
    const int rem   = K & 7;
    int kq = 0;      // slot8-advance of k: k + (k>>3), += 9 per round of 8
    int kw = 0;      // weight base index

    for (int it = 0; it < nfull; ++it, kq += 9, kw += 8) {
        #pragma unroll
        for (int kk2 = 0; kk2 < 4; ++kk2) {
            // two packed (w,w) weights per 16B shared load (broadcast)
            ulonglong2 wp = *(const ulonglong2*)&s_w[kw + 2 * kk2];
            {
                const int kk = 2 * kk2;
                #pragma unroll
                for (int i = 0; i < OPT; ++i)
                    acc[i] = fma2(wp.x, win[(kk + i) & 7], acc[i]);
                // refill position toff+kw+kk+8 -> offset kq + slot8(kk+8) = kq+kk+9
                win[kk] = *(const ull*)(pu + kq + kk + 9);
            }
            {
                const int kk = 2 * kk2 + 1;
                #pragma unroll
                for (int i = 0; i < OPT; ++i)
                    acc[i] = fma2(wp.y, win[(kk + i) & 7], acc[i]);
                win[kk] = *(const ull*)(pu + kq + kk + 9);
            }
        }
    }
    // remainder (rem < 8), predicated; refills stay within staged range
    #pragma unroll
    for (int kk = 0; kk < 7; ++kk) {
        if (kk < rem) {
            ull wv = *(const ull*)&s_w[kw + kk];
            #pragma unroll
            for (int i = 0; i < OPT; ++i)
                acc[i] = fma2(wv, win[(kk + i) & 7], acc[i]);
            win[kk] = *(const ull*)(pu + kq + kk + 9);
        }
    }

    // store: row r0 gets .x lane, row r0+1 gets .y lane
    float2 res[OPT];
    #pragma unroll
    for (int i = 0; i < OPT; ++i) res[i] = *(float2*)&acc[i];

    const long o0 = r0 * (long)T_out;
    if (t0 + OPT <= T_out) {
        float4* p0 = (float4*)(out + o0 + t0);
        float4* p1 = (float4*)(out + o0 + T_out + t0);
        p0[0] = make_float4(res[0].x, res[1].x, res[2].x, res[3].x);
        p0[1] = make_float4(res[4].x, res[5].x, res[6].x, res[7].x);
        p1[0] = make_float4(res[0].y, res[1].y, res[2].y, res[3].y);
        p1[1] = make_float4(res[4].y, res[5].y, res[6].y, res[7].y);
    } else {
        #pragma unroll
        for (int i = 0; i < OPT; ++i) {
            int t = t0 + i;
            if (t < T_out) {
                out[o0 + t]         = res[i].x;
                out[o0 + T_out + t] = res[i].y;
            }
        }
    }
}

// Robust fallback for any shape the fast path doesn't cover.
__global__ void conv_naive(const float* __restrict__ u, const float* __restrict__ kern,
                           float* __restrict__ out, int T_out, int T_in, int K, long total)
{
    long idx = (long)blockIdx.x * blockDim.x + threadIdx.x;
    if (idx >= total) return;
    int  t = (int)(idx % T_out);
    long r = idx / T_out;
    const float* up = u + r * (long)T_in + t;
    float acc = 0.0f;
    for (int k = 0; k < K; ++k)
        acc = fmaf(kern[K - 1 - k], up[k], acc);
    out[idx] = acc;
}

extern "C" void kernel_launch(void* const* d_in, const int* in_sizes, int n_in,
                              void* d_out, int out_size)
{
    const float* u    = (const float*)d_in[0];
    const float* kern = (const float*)d_in[1];
    float*       out  = (float*)d_out;

    const long n_u   = in_sizes[0];
    const int  K     = in_sizes[1];
    const long n_out = out_size;

    // u is (R, T_out + K - 1), out is (R, T_out)  =>  R = (n_u - n_out)/(K-1)
    long R = 1;
    if (K > 1 && (n_u - n_out) % (K - 1) == 0) {
        long r = (n_u - n_out) / (K - 1);
        if (r > 0 && n_out % r == 0 && n_u % r == 0) R = r;
    } else if (K == 1 && n_u == n_out) {
        R = 1;
    }
    const int T_out = (int)(n_out / R);
    const int T_in  = (int)(n_u / R);

    const bool fast = (K >= 1) && (K <= KMAX) && (R % 2 == 0) &&
                      (T_in % 4 == 0) && (T_out % 4 == 0) &&
                      (R * (long)T_out == n_out) && (R * (long)T_in == n_u) &&
                      (T_in >= T_out + K - 1);

    if (fast) {
        dim3 grid((T_out + TT - 1) / TT, (unsigned)(R / 2));
        conv2row<<<grid, BLOCK>>>(u, kern, out, T_out, T_in, K);
    } else {
        long total = n_out;
        int  thr = 256;
        long blocks = (total + thr - 1) / thr;
        conv_naive<<<(unsigned)blocks, thr>>>(u, kern, out, T_out, T_in, K, total);
    }
}

// round 16
// speedup vs baseline: 1.1717x; 1.0379x over previous
#include <cuda_runtime.h>
#include <cstdint>

// out[r,t] = sum_{k=0}^{K-1} kernel[K-1-k] * u[r, t+k]
// Two batch rows packed into f32x2 lanes, 8 outputs/thread via register ring,
// packed fma.rn.f32x2, pad-per-8 SMEM swizzle with fully hoisted address
// arithmetic (immediate-offset LDS), 4 CTAs/SM pinned (32 warps).

#define BLOCK 256
#define OPT   8
#define TT    (BLOCK * OPT)      // 2048 outputs per block (per row pair)
#define KMAX  128
#define LOADN (TT + KMAX)        // 2176 input positions staged per block

typedef unsigned long long ull;

__device__ __forceinline__ ull fma2(ull a, ull b, ull c) {
    ull d;
    asm("fma.rn.f32x2 %0, %1, %2, %3;" : "=l"(d) : "l"(a), "l"(b), "l"(c));
    return d;
}

// pad 1 float2 per 8 -> stride-8-float2 accesses land 9 apart: 16-lane phases
// hit 16 distinct even bank-pairs -> conflict-free LDS.64
__device__ __forceinline__ int slot8(int i) { return i + (i >> 3); }

__global__ __launch_bounds__(BLOCK, 4)
void conv2row(const float* __restrict__ u, const float* __restrict__ kern,
              float* __restrict__ out, int T_out, int T_in, int K)
{
    __shared__ float2 s_u[LOADN + (LOADN >> 3) + 2];   // padded layout
    __shared__ __align__(16) float2 s_w[KMAX];

    const int tid  = threadIdx.x;
    const int base = blockIdx.x * TT;
    const long r0  = (long)blockIdx.y * 2;
    const float* __restrict__ u0 = u + r0 * (long)T_in;
    const float* __restrict__ u1 = u0 + T_in;

    // reversed kernel, broadcast-packed (w,w); zero padded to KMAX
    for (int i = tid; i < KMAX; i += BLOCK) {
        float w = (i < K) ? kern[K - 1 - i] : 0.0f;
        s_w[i] = make_float2(w, w);
    }

    // stage input tile: s_u[slot8(i)] = (u0[base+i], u1[base+i])
    for (int i = tid * 4; i < LOADN; i += BLOCK * 4) {
        int g = base + i;
        float4 a, b;
        if (g + 3 < T_in) {
            a = *(const float4*)(u0 + g);
            b = *(const float4*)(u1 + g);
        } else {
            float av[4], bv[4];
            #pragma unroll
            for (int e = 0; e < 4; ++e) {
                int gg = g + e;
                av[e] = (gg < T_in) ? u0[gg] : 0.0f;
                bv[e] = (gg < T_in) ? u1[gg] : 0.0f;
            }
            a = make_float4(av[0], av[1], av[2], av[3]);
            b = make_float4(bv[0], bv[1], bv[2], bv[3]);
        }
        s_u[slot8(i + 0)] = make_float2(a.x, b.x);
        s_u[slot8(i + 1)] = make_float2(a.y, b.y);
        s_u[slot8(i + 2)] = make_float2(a.z, b.z);
        s_u[slot8(i + 3)] = make_float2(a.w, b.w);
    }
    __syncthreads();

    const int toff = tid * OPT;          // multiple of 8
    const int t0   = base + toff;
    if (t0 >= T_out) return;             // no barriers after this point

    // toff % 8 == 0 => slot8(toff + x) == slot8(toff) + slot8(x) exactly.
    // All inner-loop shared addresses become [pu + kq + imm].
    const float2* __restrict__ pu = s_u + slot8(toff);

    ull acc[OPT];
    #pragma unroll
    for (int i = 0; i < OPT; ++i) acc[i] = 0ull;

    // ring: before weight step m, win[(m+i)&7] = packed u at position toff+m+i
    ull win[OPT];
    #pragma unroll
    for (int j = 0; j < OPT; ++j) win[j] = *(const ull*)(pu + j);  // slot8(j)==j for j<8

    const int nfull = K >> 3;
    const int rem   = K & 7;
    int kq = 0;      // slot8-advance of k: k + (k>>3), += 9 per round of 8
    int kw = 0;      // weight base index

    for (int it = 0; it < nfull; ++it, kq += 9, kw += 8) {
        #pragma unroll
        for (int kk2 = 0; kk2 < 4; ++kk2) {
            // two packed (w,w) weights per 16B shared load (broadcast)
            ulonglong2 wp = *(const ulonglong2*)&s_w[kw + 2 * kk2];
            {
                const int kk = 2 * kk2;
                #pragma unroll
                for (int i = 0; i < OPT; ++i)
                    acc[i] = fma2(wp.x, win[(kk + i) & 7], acc[i]);
                // refill position toff+kw+kk+8 -> offset kq + slot8(kk+8) = kq+kk+9
                win[kk] = *(const ull*)(pu + kq + kk + 9);
            }
            {
                const int kk = 2 * kk2 + 1;
                #pragma unroll
                for (int i = 0; i < OPT; ++i)
                    acc[i] = fma2(wp.y, win[(kk + i) & 7], acc[i]);
                win[kk] = *(const ull*)(pu + kq + kk + 9);
            }
        }
    }
    // remainder (rem < 8), predicated; refills stay within staged range
    #pragma unroll
    for (int kk = 0; kk < 7; ++kk) {
        if (kk < rem) {
            ull wv = *(const ull*)&s_w[kw + kk];
            #pragma unroll
            for (int i = 0; i < OPT; ++i)
                acc[i] = fma2(wv, win[(kk + i) & 7], acc[i]);
            win[kk] = *(const ull*)(pu + kq + kk + 9);
        }
    }

    // store: row r0 gets .x lane, row r0+1 gets .y lane
    float2 res[OPT];
    #pragma unroll
    for (int i = 0; i < OPT; ++i) res[i] = *(float2*)&acc[i];

    const long o0 = r0 * (long)T_out;
    if (t0 + OPT <= T_out) {
        float4* p0 = (float4*)(out + o0 + t0);
        float4* p1 = (float4*)(out + o0 + T_out + t0);
        p0[0] = make_float4(res[0].x, res[1].x, res[2].x, res[3].x);
        p0[1] = make_float4(res[4].x, res[5].x, res[6].x, res[7].x);
        p1[0] = make_float4(res[0].y, res[1].y, res[2].y, res[3].y);
        p1[1] = make_float4(res[4].y, res[5].y, res[6].y, res[7].y);
    } else {
        #pragma unroll
        for (int i = 0; i < OPT; ++i) {
            int t = t0 + i;
            if (t < T_out) {
                out[o0 + t]         = res[i].x;
                out[o0 + T_out + t] = res[i].y;
            }
        }
    }
}

// Robust fallback for any shape the fast path doesn't cover.
__global__ void conv_naive(const float* __restrict__ u, const float* __restrict__ kern,
                           float* __restrict__ out, int T_out, int T_in, int K, long total)
{
    long idx = (long)blockIdx.x * blockDim.x + threadIdx.x;
    if (idx >= total) return;
    int  t = (int)(idx % T_out);
    long r = idx / T_out;
    const float* up = u + r * (long)T_in + t;
    float acc = 0.0f;
    for (int k = 0; k < K; ++k)
        acc = fmaf(kern[K - 1 - k], up[k], acc);
    out[idx] = acc;
}

extern "C" void kernel_launch(void* const* d_in, const int* in_sizes, int n_in,
                              void* d_out, int out_size)
{
    const float* u    = (const float*)d_in[0];
    const float* kern = (const float*)d_in[1];
    float*       out  = (float*)d_out;

    const long n_u   = in_sizes[0];
    const int  K     = in_sizes[1];
    const long n_out = out_size;

    // u is (R, T_out + K - 1), out is (R, T_out)  =>  R = (n_u - n_out)/(K-1)
    long R = 1;
    if (K > 1 && (n_u - n_out) % (K - 1) == 0) {
        long r = (n_u - n_out) / (K - 1);
        if (r > 0 && n_out % r == 0 && n_u % r == 0) R = r;
    } else if (K == 1 && n_u == n_out) {
        R = 1;
    }
    const int T_out = (int)(n_out / R);
    const int T_in  = (int)(n_u / R);

    const bool fast = (K >= 1) && (K <= KMAX) && (R % 2 == 0) &&
                      (T_in % 4 == 0) && (T_out % 4 == 0) &&
                      (R * (long)T_out == n_out) && (R * (long)T_in == n_u) &&
                      (T_in >= T_out + K - 1);

    if (fast) {
        dim3 grid((T_out + TT - 1) / TT, (unsigned)(R / 2));
        conv2row<<<grid, BLOCK>>>(u, kern, out, T_out, T_in, K);
    } else {
        long total = n_out;
        int  thr = 256;
        long blocks = (total + thr - 1) / thr;
        conv_naive<<<(unsigned)blocks, thr>>>(u, kern, out, T_out, T_in, K, total);
    }
}